// round 11
// baseline (speedup 1.0000x reference)
#include <cuda_runtime.h>
#include <cuda_bf16.h>
#include <math.h>
#include <stdint.h>

// Shapes fixed: B=4, S=2048, D=1024, H=16, dh=64.
#define BATCH     4
#define SEQ       2048
#define DMODEL    1024
#define NHEADS    16
#define HDIM      64
#define MTOT      (BATCH * SEQ)      // 8192
#define KDIM      DMODEL
#define NDIM      DMODEL
#define QKV_ELEMS (BATCH * NHEADS * SEQ * HDIM)   // 8388608

// Scratch: 6 x 16 MiB bf16 + 32 MiB fp32 + tables = 128.5 MiB total
// (footprint proven safe against the allocation guard across rounds 1-10).
__device__ __nv_bfloat16 g_qh[QKV_ELEMS];   // Q hi/lo: scaled 1/8, RoPE'd, [b,h,s,d]
__device__ __nv_bfloat16 g_ql[QKV_ELEMS];
__device__ __nv_bfloat16 g_kh[QKV_ELEMS];   // K hi/lo: RoPE'd, [b,h,s,d]
__device__ __nv_bfloat16 g_kl[QKV_ELEMS];
__device__ __nv_bfloat16 g_vh[QKV_ELEMS];   // V hi/lo TRANSPOSED: [b,h,d,s]
__device__ __nv_bfloat16 g_vl[QKV_ELEMS];
__device__ float         g_o [BATCH * SEQ * DMODEL];
__device__ float         g_cos[SEQ * (HDIM / 2)];
__device__ float         g_sin[SEQ * (HDIM / 2)];

// ---------------------------------------------------------------------------
// helpers
// ---------------------------------------------------------------------------
__device__ __forceinline__ uint32_t f2tf32(float x) {
    uint32_t u;
    asm("cvt.rna.tf32.f32 %0, %1;" : "=r"(u) : "f"(x));
    return u;
}
__device__ __forceinline__ void mma_tf32(float c[4], const uint32_t a[4],
                                         uint32_t b0, uint32_t b1) {
    asm volatile(
        "mma.sync.aligned.m16n8k8.row.col.f32.tf32.tf32.f32 "
        "{%0,%1,%2,%3}, {%4,%5,%6,%7}, {%8,%9}, {%0,%1,%2,%3};"
        : "+f"(c[0]), "+f"(c[1]), "+f"(c[2]), "+f"(c[3])
        : "r"(a[0]), "r"(a[1]), "r"(a[2]), "r"(a[3]), "r"(b0), "r"(b1));
}
__device__ __forceinline__ void mma_bf16(float c[4], const uint32_t a[4],
                                         uint32_t b0, uint32_t b1) {
    asm volatile(
        "mma.sync.aligned.m16n8k16.row.col.f32.bf16.bf16.f32 "
        "{%0,%1,%2,%3}, {%4,%5,%6,%7}, {%8,%9}, {%0,%1,%2,%3};"
        : "+f"(c[0]), "+f"(c[1]), "+f"(c[2]), "+f"(c[3])
        : "r"(a[0]), "r"(a[1]), "r"(a[2]), "r"(a[3]), "r"(b0), "r"(b1));
}
// ldmatrix x4: four 8x8 b16 tiles; lane l supplies row (l&7) of tile (l>>3).
__device__ __forceinline__ void ldsm_x4(uint32_t r[4], uint32_t addr) {
    asm volatile("ldmatrix.sync.aligned.m8n8.x4.shared.b16 {%0,%1,%2,%3}, [%4];"
        : "=r"(r[0]), "=r"(r[1]), "=r"(r[2]), "=r"(r[3]) : "r"(addr));
}
// pack two fp32 -> bf16x2; first operand lands in the HIGH half.
__device__ __forceinline__ uint32_t packbf(float hi, float lo) {
    uint32_t r;
    asm("cvt.rn.bf16x2.f32 %0, %1, %2;" : "=r"(r) : "f"(hi), "f"(lo));
    return r;
}
__device__ __forceinline__ uint4 cvt4(float4 f) {
    return make_uint4(f2tf32(f.x), f2tf32(f.y), f2tf32(f.z), f2tf32(f.w));
}
__device__ __forceinline__ uint32_t smem_u32(const void* p) {
    uint32_t a;
    asm("{ .reg .u64 t; cvta.to.shared.u64 t, %1; cvt.u32.u64 %0, t; }"
        : "=r"(a) : "l"(p));
    return a;
}
__device__ __forceinline__ void cp16(uint32_t dst, const void* src) {
    asm volatile("cp.async.ca.shared.global [%0], [%1], 16;"
                 :: "r"(dst), "l"(src));
}
#define CP_COMMIT() asm volatile("cp.async.commit_group;" ::: "memory")
#define CP_WAIT(n)  asm volatile("cp.async.wait_group %0;" :: "n"(n) : "memory")

// ---------------------------------------------------------------------------
// RoPE table
// ---------------------------------------------------------------------------
__global__ void rope_table_kernel(const int* __restrict__ tpos) {
    int s = blockIdx.x;
    int f = threadIdx.x;
    double inv = exp(-(2.0 * (double)f / (double)HDIM) * log(10000.0));
    double a = (double)tpos[s] * inv;
    g_cos[s * 32 + f] = (float)cos(a);
    g_sin[s * 32 + f] = (float)sin(a);
}

// ---------------------------------------------------------------------------
// tf32 mma.sync GEMM: reg-staged LDG + TWO smem stages so the cvt+STS fill
// of chunk ch+1 interleaves with the LDSM+MMA phase of chunk ch (one barrier
// per chunk). CTA 128x128, 8 warps (4m x 2n), KC=32 chunks, pitch 36.
// Epilogues:
//  mode 0: Q -> RoPE, *0.125, bf16 hi/lo split -> g_qh/g_ql [b,h,s,d]
//  mode 1: K -> RoPE,          bf16 hi/lo split -> g_kh/g_kl [b,h,s,d]
//  mode 2: V ->                bf16 hi/lo split -> g_vh/g_vl TRANSPOSED [b,h,d,s]
//  mode 3: plain fp32 store to Cout (A = g_o).
// ---------------------------------------------------------------------------
#define KC      32
#define PITCH   36
#define NCHUNK  (KDIM / KC)               // 32
#define STG     (128 * PITCH)             // 4608 u32 per matrix
#define STAGE_B (2 * STG * 4)             // 36864 bytes per stage (A+B)
#define GEMM_SMEM (2 * STAGE_B)           // 73728 bytes

__global__ __launch_bounds__(256, 2)
void gemm_mma(const float* __restrict__ A,
              const float* __restrict__ W0, const float* __restrict__ W1,
              const float* __restrict__ W2,
              float* __restrict__ Cout) {
    extern __shared__ __align__(16) uint32_t smu[];

    const int mode = Cout ? 3 : blockIdx.z;
    const float* W = (mode == 1) ? W1 : (mode == 2) ? W2 : W0;
    const float* Ap = A ? A : g_o;

    const int tid = threadIdx.x;
    const int warp = tid >> 5, lane = tid & 31;
    const int wm = warp >> 1, wn = warp & 1;
    const int g = lane >> 2, t = lane & 3;
    const int m0 = blockIdx.y * 128, n0 = blockIdx.x * 128;

    // ldmatrix per-lane addresses (stage-0 relative byte offsets)
    const uint32_t sb0 = smem_u32(smu);
    const int lrow = lane & 7, lm = lane >> 3;
    uint32_t aAddr[2], bAddr[4];
#pragma unroll
    for (int mf = 0; mf < 2; mf++) {
        int row = wm * 32 + mf * 16 + (lm & 1) * 8 + lrow;
        int col = (lm >> 1) * 4;
        aAddr[mf] = sb0 + (uint32_t)(row * PITCH + col) * 4;
    }
#pragma unroll
    for (int fg = 0; fg < 4; fg++) {
        int row = wn * 64 + (2 * fg + (lm >> 1)) * 8 + lrow;
        int col = (lm & 1) * 4;
        bAddr[fg] = sb0 + (uint32_t)(STG + row * PITCH + col) * 4;
    }

    // fill mapping: thread covers rows r0+32j (j<4) at k-cols q0..q0+3
    const int r0 = tid >> 3, q0 = (tid & 7) * 4;
    const float* Aptr = Ap + (size_t)(m0 + r0) * KDIM + q0;
    const float* Wptr = W  + (size_t)(n0 + r0) * KDIM + q0;

    float c[2][8][4];
#pragma unroll
    for (int mf = 0; mf < 2; mf++)
#pragma unroll
        for (int f = 0; f < 8; f++)
#pragma unroll
            for (int i = 0; i < 4; i++) c[mf][f][i] = 0.f;

    float4 ra[4], rb[4];
    // prologue: chunk 0 -> regs -> stage 0; chunk 1 -> regs (in flight)
#pragma unroll
    for (int j = 0; j < 4; j++) {
        ra[j] = *(const float4*)(Aptr + (size_t)(32 * j) * KDIM);
        rb[j] = *(const float4*)(Wptr + (size_t)(32 * j) * KDIM);
    }
#pragma unroll
    for (int j = 0; j < 4; j++) {
        const int r = r0 + 32 * j;
        *(uint4*)(smu + r * PITCH + q0) = cvt4(ra[j]);
        *(uint4*)(smu + STG + r * PITCH + q0) = cvt4(rb[j]);
    }
    __syncthreads();
#pragma unroll
    for (int j = 0; j < 4; j++) {
        ra[j] = *(const float4*)(Aptr + KC + (size_t)(32 * j) * KDIM);
        rb[j] = *(const float4*)(Wptr + KC + (size_t)(32 * j) * KDIM);
    }

    for (int ch = 0; ch < NCHUNK; ch++) {
        const uint32_t so = (uint32_t)(ch & 1) * STAGE_B;

        // fill chunk ch+1 into the other stage; then issue LDGs for ch+2
        if (ch + 1 < NCHUNK) {
            uint32_t* An = smu + ((ch + 1) & 1) * (2 * STG);
            uint32_t* Bn = An + STG;
#pragma unroll
            for (int j = 0; j < 4; j++) {
                const int r = r0 + 32 * j;
                *(uint4*)(An + r * PITCH + q0) = cvt4(ra[j]);
                *(uint4*)(Bn + r * PITCH + q0) = cvt4(rb[j]);
            }
            if (ch + 2 < NCHUNK) {
                const float* An2 = Aptr + (ch + 2) * KC;
                const float* Wn2 = Wptr + (ch + 2) * KC;
#pragma unroll
                for (int j = 0; j < 4; j++) {
                    ra[j] = *(const float4*)(An2 + (size_t)(32 * j) * KDIM);
                    rb[j] = *(const float4*)(Wn2 + (size_t)(32 * j) * KDIM);
                }
            }
        }

        // MMA phase on stage (ch&1)
#pragma unroll
        for (int ks = 0; ks < 4; ks++) {
            const uint32_t kb = so + ks * 32;
            uint32_t a[2][4];
            ldsm_x4(a[0], aAddr[0] + kb);
            ldsm_x4(a[1], aAddr[1] + kb);
#pragma unroll
            for (int fg = 0; fg < 4; fg++) {
                uint32_t bb[4];
                ldsm_x4(bb, bAddr[fg] + kb);
                mma_tf32(c[0][2 * fg],     a[0], bb[0], bb[1]);
                mma_tf32(c[1][2 * fg],     a[1], bb[0], bb[1]);
                mma_tf32(c[0][2 * fg + 1], a[0], bb[2], bb[3]);
                mma_tf32(c[1][2 * fg + 1], a[1], bb[2], bb[3]);
            }
        }
        __syncthreads();   // MMA reads (this stage) + fills (other stage) done
    }

    // Epilogue. c[mf][f]: rows (g, g+8), cols (2t, 2t+1) — RoPE pairs.
#pragma unroll
    for (int mf = 0; mf < 2; mf++) {
#pragma unroll
        for (int f = 0; f < 8; f++) {
            const float* cc = c[mf][f];
            const int col = n0 + wn * 64 + f * 8 + 2 * t;
            const int rbase = m0 + wm * 32 + mf * 16 + g;
#pragma unroll
            for (int half = 0; half < 2; half++) {
                const int m = rbase + half * 8;
                float v1 = cc[half * 2], v2 = cc[half * 2 + 1];
                if (mode == 3) {
                    *(float2*)(Cout + (size_t)m * NDIM + col) = make_float2(v1, v2);
                } else {
                    const int b = m >> 11, s = m & 2047;
                    const int h = col >> 6, d = col & 63;   // d even
                    if (mode < 2) {     // RoPE for Q and K
                        const float cs = g_cos[s * 32 + (d >> 1)];
                        const float sn = g_sin[s * 32 + (d >> 1)];
                        float r1 = v1 * cs - v2 * sn;
                        float r2 = v1 * sn + v2 * cs;
                        if (mode == 0) { r1 *= 0.125f; r2 *= 0.125f; }
                        v1 = r1; v2 = r2;
                    }
                    __nv_bfloat16 h1 = __float2bfloat16(v1);
                    __nv_bfloat16 h2 = __float2bfloat16(v2);
                    __nv_bfloat16 l1 = __float2bfloat16(v1 - __bfloat162float(h1));
                    __nv_bfloat16 l2 = __float2bfloat16(v2 - __bfloat162float(h2));
                    if (mode == 2) {    // V transposed: [b,h,d,s]
                        const size_t vb =
                            ((size_t)(b * NHEADS + h) * HDIM + d) * SEQ + s;
                        g_vh[vb] = h1;       g_vl[vb] = l1;
                        g_vh[vb + SEQ] = h2; g_vl[vb + SEQ] = l2;
                    } else {            // Q/K: [b,h,s,d], pair = one u32
                        const size_t base =
                            ((size_t)(b * NHEADS + h) * SEQ + s) * HDIM + d;
                        uint32_t hp = ((uint32_t)__bfloat16_as_ushort(h2) << 16)
                                    | __bfloat16_as_ushort(h1);
                        uint32_t lp = ((uint32_t)__bfloat16_as_ushort(l2) << 16)
                                    | __bfloat16_as_ushort(l1);
                        if (mode == 0) {
                            *(uint32_t*)(g_qh + base) = hp;
                            *(uint32_t*)(g_ql + base) = lp;
                        } else {
                            *(uint32_t*)(g_kh + base) = hp;
                            *(uint32_t*)(g_kl + base) = lp;
                        }
                    }
                }
            }
        }
    }
}

// ---------------------------------------------------------------------------
// Causal flash attention: bf16 m16n8k16 mma, 3-product hi/lo split, ldmatrix
// frag loads, cp.async DOUBLE-BUFFERED K/V tiles (prefetch kt+1 during kt).
// Br=Bc=64, 128 threads (4 warps x 16 Q-rows).
// smem per stage: Kh,Kl,Vh,Vl @ 64 x 72 bf16 (pitch 36 u32) = 36864 B; x2.
// ---------------------------------------------------------------------------
#define KP 36                        // u32 pitch
#define KTSZ (64 * KP)               // 2304 u32 per tile
#define ASTAGE_B (4 * KTSZ * 4)      // 36864 bytes per stage
#define ATTN_SMEM (2 * ASTAGE_B)     // 73728 bytes

__global__ __launch_bounds__(128)
void flash_bf16() {
    extern __shared__ __align__(16) uint32_t sm[];

    const int qt = gridDim.x - 1 - (int)blockIdx.x;   // heavy tiles first
    const int bh = blockIdx.y;
    const int tid = threadIdx.x;
    const int warp = tid >> 5, lane = tid & 31;
    const int g = lane >> 2, t = lane & 3;
    const int wr = warp * 16;

    const uint32_t smb = smem_u32(sm);
    const int lrow = lane & 7, lm = lane >> 3;
    uint32_t pat[4];
#pragma unroll
    for (int jg = 0; jg < 4; jg++) {
        int row = (2 * jg + (lm >> 1)) * 8 + lrow;   // (b0,b1) of j, j+1
        int col = (lm & 1) * 4;
        pat[jg] = smb + (uint32_t)(row * KP + col) * 4;
    }

    const uint32_t* Khg = (const uint32_t*)g_kh;
    const uint32_t* Klg = (const uint32_t*)g_kl;
    const uint32_t* Vhg = (const uint32_t*)g_vh;
    const uint32_t* Vlg = (const uint32_t*)g_vl;
    const size_t kbase0 = ((size_t)bh * SEQ) * (HDIM / 2);
    const size_t vbase0 = ((size_t)bh * HDIM) * (SEQ / 2);

    // prefetch helper values for this thread
    const int pr[4] = { (tid) >> 3, (tid + 128) >> 3, (tid + 256) >> 3, (tid + 384) >> 3 };
    const int pc = (tid & 7) * 4;

    // ---- prefetch tile kt=0 into stage 0 ----
    {
        const size_t kb = kbase0, vb = vbase0;
#pragma unroll
        for (int j = 0; j < 4; j++) {
            const int r = pr[j];
            const uint32_t ds = smb + (uint32_t)(r * KP + pc) * 4;
            cp16(ds,                Khg + kb + r * 32 + pc);
            cp16(ds + KTSZ * 4,     Klg + kb + r * 32 + pc);
            cp16(ds + 2 * KTSZ * 4, Vhg + vb + (size_t)r * (SEQ / 2) + pc);
            cp16(ds + 3 * KTSZ * 4, Vlg + vb + (size_t)r * (SEQ / 2) + pc);
        }
        CP_COMMIT();
    }

    // ---- Q fragments -> registers (u32 = bf16x2, k-pairs 2t,2t+1) ----
    const uint32_t* Qhg = (const uint32_t*)g_qh;
    const uint32_t* Qlg = (const uint32_t*)g_ql;
    const size_t qrow0 = (((size_t)bh * SEQ + qt * 64 + wr + g) * HDIM) >> 1;
    const size_t qrow1 = qrow0 + (8 * HDIM >> 1);
    uint32_t qh[4][4], ql[4][4];
#pragma unroll
    for (int k0 = 0; k0 < 4; k0++) {
        const int o8 = 8 * k0 + t;
        qh[k0][0] = Qhg[qrow0 + o8];     ql[k0][0] = Qlg[qrow0 + o8];
        qh[k0][1] = Qhg[qrow1 + o8];     ql[k0][1] = Qlg[qrow1 + o8];
        qh[k0][2] = Qhg[qrow0 + o8 + 4]; ql[k0][2] = Qlg[qrow0 + o8 + 4];
        qh[k0][3] = Qhg[qrow1 + o8 + 4]; ql[k0][3] = Qlg[qrow1 + o8 + 4];
    }

    float m_i[2] = {-1e30f, -1e30f};
    float l_i[2] = {0.f, 0.f};
    float o[8][4];
#pragma unroll
    for (int j = 0; j < 8; j++)
#pragma unroll
        for (int i = 0; i < 4; i++) o[j][i] = 0.f;

    for (int kt = 0; kt <= qt; kt++) {
        const uint32_t so = (uint32_t)(kt & 1) * ASTAGE_B;

        if (kt < qt) {   // prefetch kt+1 into the other stage
            const uint32_t sb = smb + ((kt + 1) & 1) * ASTAGE_B;
            const size_t kb = kbase0 + (size_t)(kt + 1) * 64 * (HDIM / 2);
            const size_t vb = vbase0 + (kt + 1) * 32;
#pragma unroll
            for (int j = 0; j < 4; j++) {
                const int r = pr[j];
                const uint32_t ds = sb + (uint32_t)(r * KP + pc) * 4;
                cp16(ds,                Khg + kb + r * 32 + pc);
                cp16(ds + KTSZ * 4,     Klg + kb + r * 32 + pc);
                cp16(ds + 2 * KTSZ * 4, Vhg + vb + (size_t)r * (SEQ / 2) + pc);
                cp16(ds + 3 * KTSZ * 4, Vlg + vb + (size_t)r * (SEQ / 2) + pc);
            }
            CP_COMMIT();
            CP_WAIT(1);      // current tile's group complete
        } else {
            CP_WAIT(0);
        }
        __syncthreads();

        // ---- S = Q K^T (hh + hl + lh), 4 k-steps of 16 ----
        float c[8][4];
#pragma unroll
        for (int j = 0; j < 8; j++)
#pragma unroll
            for (int i = 0; i < 4; i++) c[j][i] = 0.f;

#pragma unroll
        for (int k0 = 0; k0 < 4; k0++) {
            const uint32_t kb = so + k0 * 32;
#pragma unroll
            for (int jg = 0; jg < 4; jg++) {
                uint32_t kh4[4], kl4[4];
                ldsm_x4(kh4, pat[jg] + kb);
                ldsm_x4(kl4, pat[jg] + KTSZ * 4 + kb);
                const int j0 = 2 * jg, j1 = 2 * jg + 1;
                mma_bf16(c[j0], qh[k0], kh4[0], kh4[1]);
                mma_bf16(c[j0], qh[k0], kl4[0], kl4[1]);
                mma_bf16(c[j0], ql[k0], kh4[0], kh4[1]);
                mma_bf16(c[j1], qh[k0], kh4[2], kh4[3]);
                mma_bf16(c[j1], qh[k0], kl4[2], kl4[3]);
                mma_bf16(c[j1], ql[k0], kh4[2], kh4[3]);
            }
        }

        // ---- causal mask (diagonal tile only) ----
        if (kt == qt) {
#pragma unroll
            for (int j = 0; j < 8; j++) {
                const int col0 = j * 8 + 2 * t;
                const int r0 = wr + g, r1 = wr + g + 8;
                if (col0 > r0)     c[j][0] = -1e30f;
                if (col0 + 1 > r0) c[j][1] = -1e30f;
                if (col0 > r1)     c[j][2] = -1e30f;
                if (col0 + 1 > r1) c[j][3] = -1e30f;
            }
        }

        // ---- online softmax (rows g and g+8) ----
        float mx0 = -1e30f, mx1 = -1e30f;
#pragma unroll
        for (int j = 0; j < 8; j++) {
            mx0 = fmaxf(mx0, fmaxf(c[j][0], c[j][1]));
            mx1 = fmaxf(mx1, fmaxf(c[j][2], c[j][3]));
        }
#pragma unroll
        for (int off = 1; off < 4; off <<= 1) {
            mx0 = fmaxf(mx0, __shfl_xor_sync(0xffffffffu, mx0, off));
            mx1 = fmaxf(mx1, __shfl_xor_sync(0xffffffffu, mx1, off));
        }
        const float mn0 = fmaxf(m_i[0], mx0);
        const float mn1 = fmaxf(m_i[1], mx1);
        const float al0 = __expf(m_i[0] - mn0);
        const float al1 = __expf(m_i[1] - mn1);
        float sum0 = 0.f, sum1 = 0.f;
#pragma unroll
        for (int j = 0; j < 8; j++) {
            c[j][0] = __expf(c[j][0] - mn0);
            c[j][1] = __expf(c[j][1] - mn0);
            c[j][2] = __expf(c[j][2] - mn1);
            c[j][3] = __expf(c[j][3] - mn1);
            sum0 += c[j][0] + c[j][1];
            sum1 += c[j][2] + c[j][3];
        }
#pragma unroll
        for (int off = 1; off < 4; off <<= 1) {
            sum0 += __shfl_xor_sync(0xffffffffu, sum0, off);
            sum1 += __shfl_xor_sync(0xffffffffu, sum1, off);
        }
        l_i[0] = l_i[0] * al0 + sum0;
        l_i[1] = l_i[1] * al1 + sum1;
        m_i[0] = mn0; m_i[1] = mn1;
#pragma unroll
        for (int j = 0; j < 8; j++) {
            o[j][0] *= al0; o[j][1] *= al0;
            o[j][2] *= al1; o[j][3] *= al1;
        }

        // ---- O += P V. bf16 k16 A-frag == this thread's C-frag cols. ----
#pragma unroll
        for (int k0 = 0; k0 < 4; k0++) {
            const int j0 = 2 * k0, j1 = 2 * k0 + 1;
            uint32_t ph[4], pl[4];
            ph[0] = packbf(c[j0][1], c[j0][0]);
            ph[1] = packbf(c[j0][3], c[j0][2]);
            ph[2] = packbf(c[j1][1], c[j1][0]);
            ph[3] = packbf(c[j1][3], c[j1][2]);
#pragma unroll
            for (int i = 0; i < 4; i++) {
                const int jj = (i < 2) ? j0 : j1;
                const int bb = (i & 1) * 2;
                float h0 = __uint_as_float(ph[i] << 16);
                float h1 = __uint_as_float(ph[i] & 0xFFFF0000u);
                pl[i] = packbf(c[jj][bb + 1] - h1, c[jj][bb] - h0);
            }
            const uint32_t kb = so + k0 * 32;
#pragma unroll
            for (int jg = 0; jg < 4; jg++) {
                uint32_t vh4[4], vl4[4];
                ldsm_x4(vh4, pat[jg] + 2 * KTSZ * 4 + kb);
                ldsm_x4(vl4, pat[jg] + 3 * KTSZ * 4 + kb);
                const int jo0 = 2 * jg, jo1 = 2 * jg + 1;
                mma_bf16(o[jo0], ph, vh4[0], vh4[1]);
                mma_bf16(o[jo0], ph, vl4[0], vl4[1]);
                mma_bf16(o[jo0], pl, vh4[0], vh4[1]);
                mma_bf16(o[jo1], ph, vh4[2], vh4[3]);
                mma_bf16(o[jo1], ph, vl4[2], vl4[3]);
                mma_bf16(o[jo1], pl, vh4[2], vh4[3]);
            }
        }
        __syncthreads();   // all reads of this stage done before its refill
    }

    // ---- epilogue: O / l -> g_o [b, s, h*64 + d] ----
    const int b = bh >> 4, h = bh & 15;
    const float inv0 = 1.f / l_i[0];
    const float inv1 = 1.f / l_i[1];
    const int s0 = qt * 64 + wr + g;
    const int s1 = s0 + 8;
    float* row0 = g_o + ((size_t)b * SEQ + s0) * DMODEL + h * HDIM;
    float* row1 = g_o + ((size_t)b * SEQ + s1) * DMODEL + h * HDIM;
#pragma unroll
    for (int j = 0; j < 8; j++) {
        const int d = j * 8 + 2 * t;
        *(float2*)(row0 + d) = make_float2(o[j][0] * inv0, o[j][1] * inv0);
        *(float2*)(row1 + d) = make_float2(o[j][2] * inv1, o[j][3] * inv1);
    }
}

// ---------------------------------------------------------------------------
extern "C" void kernel_launch(void* const* d_in, const int* in_sizes, int n_in,
                              void* d_out, int out_size) {
    const float* x  = (const float*)d_in[0];
    const float* Wq = (const float*)d_in[1];
    const float* Wk = (const float*)d_in[2];
    const float* Wv = (const float*)d_in[3];
    const float* Wo = (const float*)d_in[4];
    const int* tpos = (const int*)d_in[5];
    float* out = (float*)d_out;

    rope_table_kernel<<<SEQ, 32>>>(tpos);

    cudaFuncSetAttribute(gemm_mma, cudaFuncAttributeMaxDynamicSharedMemorySize,
                         GEMM_SMEM);
    cudaFuncSetAttribute(flash_bf16, cudaFuncAttributeMaxDynamicSharedMemorySize,
                         ATTN_SMEM);

    dim3 gqkv(NDIM / 128, MTOT / 128, 3);
    gemm_mma<<<gqkv, 256, GEMM_SMEM>>>(x, Wq, Wk, Wv, nullptr);

    flash_bf16<<<dim3(SEQ / 64, BATCH * NHEADS), 128, ATTN_SMEM>>>();

    dim3 gp(NDIM / 128, MTOT / 128, 1);
    gemm_mma<<<gp, 256, GEMM_SMEM>>>(nullptr, Wo, nullptr, nullptr, out);
}

// round 12
// speedup vs baseline: 1.0458x; 1.0458x over previous
#include <cuda_runtime.h>
#include <cuda_bf16.h>
#include <math.h>
#include <stdint.h>

// Shapes fixed: B=4, S=2048, D=1024, H=16, dh=64.
#define BATCH     4
#define SEQ       2048
#define DMODEL    1024
#define NHEADS    16
#define HDIM      64
#define MTOT      (BATCH * SEQ)      // 8192
#define KDIM      DMODEL
#define NDIM      DMODEL
#define WELEM     (DMODEL * DMODEL)  // 1048576
#define QKV_ELEMS (BATCH * NHEADS * SEQ * HDIM)   // 8388608

// Scratch: 96 MiB bf16 QKV + 32 MiB g_o(tf32) + 16 MiB tf32 weights + tables
// = 144.5 MiB (round-6 guard data implies allowance ~176 MiB).
__device__ __nv_bfloat16 g_qh[QKV_ELEMS];   // Q hi/lo: scaled 1/8, RoPE'd, [b,h,s,d]
__device__ __nv_bfloat16 g_ql[QKV_ELEMS];
__device__ __nv_bfloat16 g_kh[QKV_ELEMS];   // K hi/lo: RoPE'd, [b,h,s,d]
__device__ __nv_bfloat16 g_kl[QKV_ELEMS];
__device__ __nv_bfloat16 g_vh[QKV_ELEMS];   // V hi/lo TRANSPOSED: [b,h,d,s]
__device__ __nv_bfloat16 g_vl[QKV_ELEMS];
__device__ uint32_t      g_o [BATCH * SEQ * DMODEL];   // attention out as tf32
__device__ uint32_t      g_wc[4 * WELEM];              // Wq,Wk,Wv,Wo as tf32
__device__ float         g_cos[SEQ * (HDIM / 2)];
__device__ float         g_sin[SEQ * (HDIM / 2)];

// ---------------------------------------------------------------------------
// helpers
// ---------------------------------------------------------------------------
__device__ __forceinline__ uint32_t f2tf32(float x) {
    uint32_t u;
    asm("cvt.rna.tf32.f32 %0, %1;" : "=r"(u) : "f"(x));
    return u;
}
__device__ __forceinline__ void mma_tf32(float c[4], const uint32_t a[4],
                                         uint32_t b0, uint32_t b1) {
    asm volatile(
        "mma.sync.aligned.m16n8k8.row.col.f32.tf32.tf32.f32 "
        "{%0,%1,%2,%3}, {%4,%5,%6,%7}, {%8,%9}, {%0,%1,%2,%3};"
        : "+f"(c[0]), "+f"(c[1]), "+f"(c[2]), "+f"(c[3])
        : "r"(a[0]), "r"(a[1]), "r"(a[2]), "r"(a[3]), "r"(b0), "r"(b1));
}
__device__ __forceinline__ void mma_bf16(float c[4], const uint32_t a[4],
                                         uint32_t b0, uint32_t b1) {
    asm volatile(
        "mma.sync.aligned.m16n8k16.row.col.f32.bf16.bf16.f32 "
        "{%0,%1,%2,%3}, {%4,%5,%6,%7}, {%8,%9}, {%0,%1,%2,%3};"
        : "+f"(c[0]), "+f"(c[1]), "+f"(c[2]), "+f"(c[3])
        : "r"(a[0]), "r"(a[1]), "r"(a[2]), "r"(a[3]), "r"(b0), "r"(b1));
}
// ldmatrix x4: four 8x8 b16 tiles; lane l supplies row (l&7) of tile (l>>3).
__device__ __forceinline__ void ldsm_x4(uint32_t r[4], uint32_t addr) {
    asm volatile("ldmatrix.sync.aligned.m8n8.x4.shared.b16 {%0,%1,%2,%3}, [%4];"
        : "=r"(r[0]), "=r"(r[1]), "=r"(r[2]), "=r"(r[3]) : "r"(addr));
}
// pack two fp32 -> bf16x2; first operand lands in the HIGH half.
__device__ __forceinline__ uint32_t packbf(float hi, float lo) {
    uint32_t r;
    asm("cvt.rn.bf16x2.f32 %0, %1, %2;" : "=r"(r) : "f"(hi), "f"(lo));
    return r;
}
__device__ __forceinline__ uint4 cvt4(float4 f) {
    return make_uint4(f2tf32(f.x), f2tf32(f.y), f2tf32(f.z), f2tf32(f.w));
}
__device__ __forceinline__ uint32_t smem_u32(const void* p) {
    uint32_t a;
    asm("{ .reg .u64 t; cvta.to.shared.u64 t, %1; cvt.u32.u64 %0, t; }"
        : "=r"(a) : "l"(p));
    return a;
}
__device__ __forceinline__ void cp16(uint32_t dst, const void* src) {
    asm volatile("cp.async.ca.shared.global [%0], [%1], 16;"
                 :: "r"(dst), "l"(src));
}
#define CP_COMMIT() asm volatile("cp.async.commit_group;" ::: "memory")
#define CP_WAIT(n)  asm volatile("cp.async.wait_group %0;" :: "n"(n) : "memory")

// ---------------------------------------------------------------------------
// RoPE table + weight pre-conversion (fp32 -> tf32, once)
// ---------------------------------------------------------------------------
__global__ void rope_table_kernel(const int* __restrict__ tpos) {
    int s = blockIdx.x;
    int f = threadIdx.x;
    double inv = exp(-(2.0 * (double)f / (double)HDIM) * log(10000.0));
    double a = (double)tpos[s] * inv;
    g_cos[s * 32 + f] = (float)cos(a);
    g_sin[s * 32 + f] = (float)sin(a);
}

__global__ __launch_bounds__(256)
void cvt_w_kernel(const float* __restrict__ w0, const float* __restrict__ w1,
                  const float* __restrict__ w2, const float* __restrict__ w3) {
    const float* src = (blockIdx.y == 0) ? w0 : (blockIdx.y == 1) ? w1
                     : (blockIdx.y == 2) ? w2 : w3;
    uint32_t* dst = g_wc + (size_t)blockIdx.y * WELEM;
    int i = (blockIdx.x * 256 + threadIdx.x) * 4;
    float4 f = *(const float4*)(src + i);
    *(uint4*)(dst + i) = cvt4(f);
}

// ---------------------------------------------------------------------------
// tf32 mma.sync GEMM. Round-10 proven core; W now pre-converted tf32 and
// streamed via a 2-stage cp.async pipeline (zero cvt/STS issue for W).
// A: QKV mode reads fp32 x (reg-staged LDG + cvt + STS, single stage);
//    proj mode reads g_o already tf32 (raw uint4 pass-through).
// CTA 128x128, 8 warps (4m x 2n), KC=32 chunks, pitch 36, ldmatrix frags.
// Epilogues: mode 0/1 Q/K RoPE + bf16 hi/lo; mode 2 V hi/lo transposed;
//            mode 3 fp32 store to Cout.
// ---------------------------------------------------------------------------
#define KC      32
#define PITCH   36
#define NCHUNK  (KDIM / KC)               // 32
#define STG     (128 * PITCH)             // 4608 u32
#define GEMM_SMEM (3 * STG * 4)           // As + Ws[2] = 55296 bytes

__global__ __launch_bounds__(256, 2)
void gemm_mma(const float* __restrict__ X, float* __restrict__ Cout) {
    extern __shared__ __align__(16) uint32_t smu[];
    uint32_t* As = smu;                    // single A stage
    // W stages at smu + STG, smu + 2*STG

    const int mode = Cout ? 3 : blockIdx.z;
    const uint32_t* Wc = g_wc + (size_t)mode * WELEM;   // mode==3 -> Wo

    const int tid = threadIdx.x;
    const int warp = tid >> 5, lane = tid & 31;
    const int wm = warp >> 1, wn = warp & 1;
    const int g = lane >> 2, t = lane & 3;
    const int m0 = blockIdx.y * 128, n0 = blockIdx.x * 128;

    const uint32_t sb0 = smem_u32(smu);
    const int lrow = lane & 7, lm = lane >> 3;
    uint32_t aAddr[2], bAddr[4];
#pragma unroll
    for (int mf = 0; mf < 2; mf++) {
        int row = wm * 32 + mf * 16 + (lm & 1) * 8 + lrow;
        int col = (lm >> 1) * 4;
        aAddr[mf] = sb0 + (uint32_t)(row * PITCH + col) * 4;
    }
#pragma unroll
    for (int fg = 0; fg < 4; fg++) {
        int row = wn * 64 + (2 * fg + (lm >> 1)) * 8 + lrow;
        int col = (lm & 1) * 4;
        bAddr[fg] = sb0 + (uint32_t)(STG + row * PITCH + col) * 4;  // W stage 0
    }

    // fill mapping: thread covers rows r0+32j (j<4) at k-cols q0..q0+3
    const int r0 = tid >> 3, q0 = (tid & 7) * 4;
    const float*    Axf = (mode == 3) ? nullptr : X + (size_t)(m0 + r0) * KDIM + q0;
    const uint32_t* Axu = (mode == 3) ? g_o + (size_t)(m0 + r0) * KDIM + q0 : nullptr;
    const uint32_t* Wptr = Wc + (size_t)(n0 + r0) * KDIM + q0;

    float c[2][8][4];
#pragma unroll
    for (int mf = 0; mf < 2; mf++)
#pragma unroll
        for (int f = 0; f < 8; f++)
#pragma unroll
            for (int i = 0; i < 4; i++) c[mf][f][i] = 0.f;

    float4 ra[4];
    uint4  ua[4];

    // ---- prologue: A(0) -> smem; W(0) -> cp.async stage 0 ----
    if (mode != 3) {
#pragma unroll
        for (int j = 0; j < 4; j++)
            ra[j] = *(const float4*)(Axf + (size_t)(32 * j) * KDIM);
#pragma unroll
        for (int j = 0; j < 4; j++)
            *(uint4*)(As + (r0 + 32 * j) * PITCH + q0) = cvt4(ra[j]);
    } else {
#pragma unroll
        for (int j = 0; j < 4; j++)
            ua[j] = *(const uint4*)(Axu + (size_t)(32 * j) * KDIM);
#pragma unroll
        for (int j = 0; j < 4; j++)
            *(uint4*)(As + (r0 + 32 * j) * PITCH + q0) = ua[j];
    }
    {
        const uint32_t wdst = sb0 + (uint32_t)(STG) * 4;   // stage 0
#pragma unroll
        for (int j = 0; j < 4; j++)
            cp16(wdst + (uint32_t)((r0 + 32 * j) * PITCH + q0) * 4,
                 Wptr + (size_t)(32 * j) * KDIM);
        CP_COMMIT();
    }

    for (int ch = 0; ch < NCHUNK; ch++) {
        // prefetch W(ch+1) into the other stage; stage A(ch+1) into regs
        if (ch + 1 < NCHUNK) {
            const int kc2 = (ch + 1) * KC;
            const uint32_t wdst = sb0 + (uint32_t)(STG * (1 + ((ch + 1) & 1))) * 4;
#pragma unroll
            for (int j = 0; j < 4; j++)
                cp16(wdst + (uint32_t)((r0 + 32 * j) * PITCH + q0) * 4,
                     Wptr + kc2 + (size_t)(32 * j) * KDIM);
            CP_COMMIT();
            if (mode != 3) {
#pragma unroll
                for (int j = 0; j < 4; j++)
                    ra[j] = *(const float4*)(Axf + kc2 + (size_t)(32 * j) * KDIM);
            } else {
#pragma unroll
                for (int j = 0; j < 4; j++)
                    ua[j] = *(const uint4*)(Axu + kc2 + (size_t)(32 * j) * KDIM);
            }
            CP_WAIT(1);     // W(ch) complete (this thread)
        } else {
            CP_WAIT(0);
        }
        __syncthreads();    // W(ch) from all threads + A(ch) STS visible

        // ---- MMA phase on As + W stage (ch&1) ----
        const uint32_t wso = (uint32_t)((ch & 1) * STG) * 4;
#pragma unroll
        for (int ks = 0; ks < 4; ks++) {
            const uint32_t kb = ks * 32;
            uint32_t a[2][4];
            ldsm_x4(a[0], aAddr[0] + kb);
            ldsm_x4(a[1], aAddr[1] + kb);
#pragma unroll
            for (int fg = 0; fg < 4; fg++) {
                uint32_t bb[4];
                ldsm_x4(bb, bAddr[fg] + wso + kb);
                mma_tf32(c[0][2 * fg],     a[0], bb[0], bb[1]);
                mma_tf32(c[1][2 * fg],     a[1], bb[0], bb[1]);
                mma_tf32(c[0][2 * fg + 1], a[0], bb[2], bb[3]);
                mma_tf32(c[1][2 * fg + 1], a[1], bb[2], bb[3]);
            }
        }
        __syncthreads();    // all warps done reading As before overwrite

        if (ch + 1 < NCHUNK) {
            if (mode != 3) {
#pragma unroll
                for (int j = 0; j < 4; j++)
                    *(uint4*)(As + (r0 + 32 * j) * PITCH + q0) = cvt4(ra[j]);
            } else {
#pragma unroll
                for (int j = 0; j < 4; j++)
                    *(uint4*)(As + (r0 + 32 * j) * PITCH + q0) = ua[j];
            }
            // visibility ensured by the sync at the top of the next iteration
        }
    }

    // Epilogue. c[mf][f]: rows (g, g+8), cols (2t, 2t+1) — RoPE pairs.
#pragma unroll
    for (int mf = 0; mf < 2; mf++) {
#pragma unroll
        for (int f = 0; f < 8; f++) {
            const float* cc = c[mf][f];
            const int col = n0 + wn * 64 + f * 8 + 2 * t;
            const int rbase = m0 + wm * 32 + mf * 16 + g;
#pragma unroll
            for (int half = 0; half < 2; half++) {
                const int m = rbase + half * 8;
                float v1 = cc[half * 2], v2 = cc[half * 2 + 1];
                if (mode == 3) {
                    *(float2*)(Cout + (size_t)m * NDIM + col) = make_float2(v1, v2);
                } else {
                    const int b = m >> 11, s = m & 2047;
                    const int h = col >> 6, d = col & 63;   // d even
                    if (mode < 2) {     // RoPE for Q and K
                        const float cs = g_cos[s * 32 + (d >> 1)];
                        const float sn = g_sin[s * 32 + (d >> 1)];
                        float r1 = v1 * cs - v2 * sn;
                        float r2 = v1 * sn + v2 * cs;
                        if (mode == 0) { r1 *= 0.125f; r2 *= 0.125f; }
                        v1 = r1; v2 = r2;
                    }
                    __nv_bfloat16 h1 = __float2bfloat16(v1);
                    __nv_bfloat16 h2 = __float2bfloat16(v2);
                    __nv_bfloat16 l1 = __float2bfloat16(v1 - __bfloat162float(h1));
                    __nv_bfloat16 l2 = __float2bfloat16(v2 - __bfloat162float(h2));
                    if (mode == 2) {    // V transposed: [b,h,d,s]
                        const size_t vb =
                            ((size_t)(b * NHEADS + h) * HDIM + d) * SEQ + s;
                        g_vh[vb] = h1;       g_vl[vb] = l1;
                        g_vh[vb + SEQ] = h2; g_vl[vb + SEQ] = l2;
                    } else {            // Q/K: [b,h,s,d], pair = one u32
                        const size_t base =
                            ((size_t)(b * NHEADS + h) * SEQ + s) * HDIM + d;
                        uint32_t hp = ((uint32_t)__bfloat16_as_ushort(h2) << 16)
                                    | __bfloat16_as_ushort(h1);
                        uint32_t lp = ((uint32_t)__bfloat16_as_ushort(l2) << 16)
                                    | __bfloat16_as_ushort(l1);
                        if (mode == 0) {
                            *(uint32_t*)(g_qh + base) = hp;
                            *(uint32_t*)(g_ql + base) = lp;
                        } else {
                            *(uint32_t*)(g_kh + base) = hp;
                            *(uint32_t*)(g_kl + base) = lp;
                        }
                    }
                }
            }
        }
    }
}

// ---------------------------------------------------------------------------
// Causal flash attention: bf16 m16n8k16 mma, 3-product hi/lo split, ldmatrix
// frag loads, cp.async double-buffered K/V tiles (round-11 proven, ~313 us).
// Epilogue now writes g_o as tf32 (u32) so the out-proj GEMM skips its cvt.
// ---------------------------------------------------------------------------
#define KP 36                        // u32 pitch
#define KTSZ (64 * KP)               // 2304 u32 per tile
#define ASTAGE_B (4 * KTSZ * 4)      // 36864 bytes per stage
#define ATTN_SMEM (2 * ASTAGE_B)     // 73728 bytes

__global__ __launch_bounds__(128)
void flash_bf16() {
    extern __shared__ __align__(16) uint32_t sm[];

    const int qt = gridDim.x - 1 - (int)blockIdx.x;   // heavy tiles first
    const int bh = blockIdx.y;
    const int tid = threadIdx.x;
    const int warp = tid >> 5, lane = tid & 31;
    const int g = lane >> 2, t = lane & 3;
    const int wr = warp * 16;

    const uint32_t smb = smem_u32(sm);
    const int lrow = lane & 7, lm = lane >> 3;
    uint32_t pat[4];
#pragma unroll
    for (int jg = 0; jg < 4; jg++) {
        int row = (2 * jg + (lm >> 1)) * 8 + lrow;   // (b0,b1) of j, j+1
        int col = (lm & 1) * 4;
        pat[jg] = smb + (uint32_t)(row * KP + col) * 4;
    }

    const uint32_t* Khg = (const uint32_t*)g_kh;
    const uint32_t* Klg = (const uint32_t*)g_kl;
    const uint32_t* Vhg = (const uint32_t*)g_vh;
    const uint32_t* Vlg = (const uint32_t*)g_vl;
    const size_t kbase0 = ((size_t)bh * SEQ) * (HDIM / 2);
    const size_t vbase0 = ((size_t)bh * HDIM) * (SEQ / 2);

    const int pr[4] = { (tid) >> 3, (tid + 128) >> 3, (tid + 256) >> 3, (tid + 384) >> 3 };
    const int pc = (tid & 7) * 4;

    // ---- prefetch tile kt=0 into stage 0 ----
    {
        const size_t kb = kbase0, vb = vbase0;
#pragma unroll
        for (int j = 0; j < 4; j++) {
            const int r = pr[j];
            const uint32_t ds = smb + (uint32_t)(r * KP + pc) * 4;
            cp16(ds,                Khg + kb + r * 32 + pc);
            cp16(ds + KTSZ * 4,     Klg + kb + r * 32 + pc);
            cp16(ds + 2 * KTSZ * 4, Vhg + vb + (size_t)r * (SEQ / 2) + pc);
            cp16(ds + 3 * KTSZ * 4, Vlg + vb + (size_t)r * (SEQ / 2) + pc);
        }
        CP_COMMIT();
    }

    // ---- Q fragments -> registers (u32 = bf16x2, k-pairs 2t,2t+1) ----
    const uint32_t* Qhg = (const uint32_t*)g_qh;
    const uint32_t* Qlg = (const uint32_t*)g_ql;
    const size_t qrow0 = (((size_t)bh * SEQ + qt * 64 + wr + g) * HDIM) >> 1;
    const size_t qrow1 = qrow0 + (8 * HDIM >> 1);
    uint32_t qh[4][4], ql[4][4];
#pragma unroll
    for (int k0 = 0; k0 < 4; k0++) {
        const int o8 = 8 * k0 + t;
        qh[k0][0] = Qhg[qrow0 + o8];     ql[k0][0] = Qlg[qrow0 + o8];
        qh[k0][1] = Qhg[qrow1 + o8];     ql[k0][1] = Qlg[qrow1 + o8];
        qh[k0][2] = Qhg[qrow0 + o8 + 4]; ql[k0][2] = Qlg[qrow0 + o8 + 4];
        qh[k0][3] = Qhg[qrow1 + o8 + 4]; ql[k0][3] = Qlg[qrow1 + o8 + 4];
    }

    float m_i[2] = {-1e30f, -1e30f};
    float l_i[2] = {0.f, 0.f};
    float o[8][4];
#pragma unroll
    for (int j = 0; j < 8; j++)
#pragma unroll
        for (int i = 0; i < 4; i++) o[j][i] = 0.f;

    for (int kt = 0; kt <= qt; kt++) {
        const uint32_t so = (uint32_t)(kt & 1) * ASTAGE_B;

        if (kt < qt) {   // prefetch kt+1 into the other stage
            const uint32_t sb = smb + ((kt + 1) & 1) * ASTAGE_B;
            const size_t kb = kbase0 + (size_t)(kt + 1) * 64 * (HDIM / 2);
            const size_t vb = vbase0 + (kt + 1) * 32;
#pragma unroll
            for (int j = 0; j < 4; j++) {
                const int r = pr[j];
                const uint32_t ds = sb + (uint32_t)(r * KP + pc) * 4;
                cp16(ds,                Khg + kb + r * 32 + pc);
                cp16(ds + KTSZ * 4,     Klg + kb + r * 32 + pc);
                cp16(ds + 2 * KTSZ * 4, Vhg + vb + (size_t)r * (SEQ / 2) + pc);
                cp16(ds + 3 * KTSZ * 4, Vlg + vb + (size_t)r * (SEQ / 2) + pc);
            }
            CP_COMMIT();
            CP_WAIT(1);
        } else {
            CP_WAIT(0);
        }
        __syncthreads();

        // ---- S = Q K^T (hh + hl + lh), 4 k-steps of 16 ----
        float c[8][4];
#pragma unroll
        for (int j = 0; j < 8; j++)
#pragma unroll
            for (int i = 0; i < 4; i++) c[j][i] = 0.f;

#pragma unroll
        for (int k0 = 0; k0 < 4; k0++) {
            const uint32_t kb = so + k0 * 32;
#pragma unroll
            for (int jg = 0; jg < 4; jg++) {
                uint32_t kh4[4], kl4[4];
                ldsm_x4(kh4, pat[jg] + kb);
                ldsm_x4(kl4, pat[jg] + KTSZ * 4 + kb);
                const int j0 = 2 * jg, j1 = 2 * jg + 1;
                mma_bf16(c[j0], qh[k0], kh4[0], kh4[1]);
                mma_bf16(c[j0], qh[k0], kl4[0], kl4[1]);
                mma_bf16(c[j0], ql[k0], kh4[0], kh4[1]);
                mma_bf16(c[j1], qh[k0], kh4[2], kh4[3]);
                mma_bf16(c[j1], qh[k0], kl4[2], kl4[3]);
                mma_bf16(c[j1], ql[k0], kh4[2], kh4[3]);
            }
        }

        // ---- causal mask (diagonal tile only) ----
        if (kt == qt) {
#pragma unroll
            for (int j = 0; j < 8; j++) {
                const int col0 = j * 8 + 2 * t;
                const int r0 = wr + g, r1 = wr + g + 8;
                if (col0 > r0)     c[j][0] = -1e30f;
                if (col0 + 1 > r0) c[j][1] = -1e30f;
                if (col0 > r1)     c[j][2] = -1e30f;
                if (col0 + 1 > r1) c[j][3] = -1e30f;
            }
        }

        // ---- online softmax (rows g and g+8) ----
        float mx0 = -1e30f, mx1 = -1e30f;
#pragma unroll
        for (int j = 0; j < 8; j++) {
            mx0 = fmaxf(mx0, fmaxf(c[j][0], c[j][1]));
            mx1 = fmaxf(mx1, fmaxf(c[j][2], c[j][3]));
        }
#pragma unroll
        for (int off = 1; off < 4; off <<= 1) {
            mx0 = fmaxf(mx0, __shfl_xor_sync(0xffffffffu, mx0, off));
            mx1 = fmaxf(mx1, __shfl_xor_sync(0xffffffffu, mx1, off));
        }
        const float mn0 = fmaxf(m_i[0], mx0);
        const float mn1 = fmaxf(m_i[1], mx1);
        const float al0 = __expf(m_i[0] - mn0);
        const float al1 = __expf(m_i[1] - mn1);
        float sum0 = 0.f, sum1 = 0.f;
#pragma unroll
        for (int j = 0; j < 8; j++) {
            c[j][0] = __expf(c[j][0] - mn0);
            c[j][1] = __expf(c[j][1] - mn0);
            c[j][2] = __expf(c[j][2] - mn1);
            c[j][3] = __expf(c[j][3] - mn1);
            sum0 += c[j][0] + c[j][1];
            sum1 += c[j][2] + c[j][3];
        }
#pragma unroll
        for (int off = 1; off < 4; off <<= 1) {
            sum0 += __shfl_xor_sync(0xffffffffu, sum0, off);
            sum1 += __shfl_xor_sync(0xffffffffu, sum1, off);
        }
        l_i[0] = l_i[0] * al0 + sum0;
        l_i[1] = l_i[1] * al1 + sum1;
        m_i[0] = mn0; m_i[1] = mn1;
#pragma unroll
        for (int j = 0; j < 8; j++) {
            o[j][0] *= al0; o[j][1] *= al0;
            o[j][2] *= al1; o[j][3] *= al1;
        }

        // ---- O += P V. bf16 k16 A-frag == this thread's C-frag cols. ----
#pragma unroll
        for (int k0 = 0; k0 < 4; k0++) {
            const int j0 = 2 * k0, j1 = 2 * k0 + 1;
            uint32_t ph[4], pl[4];
            ph[0] = packbf(c[j0][1], c[j0][0]);
            ph[1] = packbf(c[j0][3], c[j0][2]);
            ph[2] = packbf(c[j1][1], c[j1][0]);
            ph[3] = packbf(c[j1][3], c[j1][2]);
#pragma unroll
            for (int i = 0; i < 4; i++) {
                const int jj = (i < 2) ? j0 : j1;
                const int bb = (i & 1) * 2;
                float h0 = __uint_as_float(ph[i] << 16);
                float h1 = __uint_as_float(ph[i] & 0xFFFF0000u);
                pl[i] = packbf(c[jj][bb + 1] - h1, c[jj][bb] - h0);
            }
            const uint32_t kb = so + k0 * 32;
#pragma unroll
            for (int jg = 0; jg < 4; jg++) {
                uint32_t vh4[4], vl4[4];
                ldsm_x4(vh4, pat[jg] + 2 * KTSZ * 4 + kb);
                ldsm_x4(vl4, pat[jg] + 3 * KTSZ * 4 + kb);
                const int jo0 = 2 * jg, jo1 = 2 * jg + 1;
                mma_bf16(o[jo0], ph, vh4[0], vh4[1]);
                mma_bf16(o[jo0], ph, vl4[0], vl4[1]);
                mma_bf16(o[jo0], pl, vh4[0], vh4[1]);
                mma_bf16(o[jo1], ph, vh4[2], vh4[3]);
                mma_bf16(o[jo1], ph, vl4[2], vl4[3]);
                mma_bf16(o[jo1], pl, vh4[2], vh4[3]);
            }
        }
        __syncthreads();   // all reads of this stage done before its refill
    }

    // ---- epilogue: O / l -> g_o [b, s, h*64 + d] as tf32 (u32) ----
    const int b = bh >> 4, h = bh & 15;
    const float inv0 = 1.f / l_i[0];
    const float inv1 = 1.f / l_i[1];
    const int s0 = qt * 64 + wr + g;
    const int s1 = s0 + 8;
    uint32_t* row0 = g_o + ((size_t)b * SEQ + s0) * DMODEL + h * HDIM;
    uint32_t* row1 = g_o + ((size_t)b * SEQ + s1) * DMODEL + h * HDIM;
#pragma unroll
    for (int j = 0; j < 8; j++) {
        const int d = j * 8 + 2 * t;
        *(uint2*)(row0 + d) = make_uint2(f2tf32(o[j][0] * inv0), f2tf32(o[j][1] * inv0));
        *(uint2*)(row1 + d) = make_uint2(f2tf32(o[j][2] * inv1), f2tf32(o[j][3] * inv1));
    }
}

// ---------------------------------------------------------------------------
extern "C" void kernel_launch(void* const* d_in, const int* in_sizes, int n_in,
                              void* d_out, int out_size) {
    const float* x  = (const float*)d_in[0];
    const float* Wq = (const float*)d_in[1];
    const float* Wk = (const float*)d_in[2];
    const float* Wv = (const float*)d_in[3];
    const float* Wo = (const float*)d_in[4];
    const int* tpos = (const int*)d_in[5];
    float* out = (float*)d_out;

    rope_table_kernel<<<SEQ, 32>>>(tpos);
    cvt_w_kernel<<<dim3(WELEM / 1024, 4), 256>>>(Wq, Wk, Wv, Wo);

    cudaFuncSetAttribute(gemm_mma, cudaFuncAttributeMaxDynamicSharedMemorySize,
                         GEMM_SMEM);
    cudaFuncSetAttribute(flash_bf16, cudaFuncAttributeMaxDynamicSharedMemorySize,
                         ATTN_SMEM);

    dim3 gqkv(NDIM / 128, MTOT / 128, 3);
    gemm_mma<<<gqkv, 256, GEMM_SMEM>>>(x, nullptr);

    flash_bf16<<<dim3(SEQ / 64, BATCH * NHEADS), 128, ATTN_SMEM>>>();

    dim3 gp(NDIM / 128, MTOT / 128, 1);
    gemm_mma<<<gp, 256, GEMM_SMEM>>>(nullptr, out);
}